// round 12
// baseline (speedup 1.0000x reference)
#include <cuda_runtime.h>
#include <cuda_fp16.h>
#include <cstdint>

// ============================================================================
// RBF: out[i][j] = exp(-0.5 * ||x_i - y_j||^2 / sigma^2), N=M=8192, D=64.
// sqd = xn_i + yn_j - 2*(x_i . y_j); cross via mma.sync fp16 HMMA, exact
// hi/lo split, 3-term hi*hi + hi*lo + lo*hi.
// R10/R11: operands pre-swizzled in GMEM into FRAGMENT-MAJOR layout; mainloop
// loads mma fragments directly with coalesced LDG.128 (no smem staging, no
// mainloop __syncthreads). Saves the 1024 wf/CTA LDG->STS fill path.
// Resubmitted verbatim after R10 infra failure.
// ============================================================================

#define NROWS 8192
#define TILE 128

// Fragment-major operand arrays.
// A: [block16 (512)][ks (4)][part hi/lo (2)][lane (32)] x uint4
// B: [nblock32 (256)][ks (4)][part (2)][nfpair (2)][lane (32)] x uint4
__device__ __align__(16) uint4 g_Af[512 * 4 * 2 * 32];       // 2 MB
__device__ __align__(16) uint4 g_Bf[256 * 4 * 2 * 2 * 32];   // 2 MB
__device__ float g_xn[NROWS];
__device__ float g_yn[NROWS];

__device__ __forceinline__ void mma16816(float* d, const uint32_t* a, const uint32_t* b) {
    asm volatile(
        "mma.sync.aligned.m16n8k16.row.col.f32.f16.f16.f32 "
        "{%0,%1,%2,%3}, {%4,%5,%6,%7}, {%8,%9}, {%0,%1,%2,%3};"
        : "+f"(d[0]), "+f"(d[1]), "+f"(d[2]), "+f"(d[3])
        : "r"(a[0]), "r"(a[1]), "r"(a[2]), "r"(a[3]), "r"(b[0]), "r"(b[1]));
}

__device__ __forceinline__ uint32_t pack_h2(__half a, __half b) {
    __half2 h = __halves2half2(a, b);
    return *reinterpret_cast<uint32_t*>(&h);
}

// ============================================================================
// prep: split fp32 -> (hi, lo) fp16; write fragment-major layouts + norms.
// One warp per source row; lane l owns k-pair (2l, 2l+1).
// ============================================================================
__global__ void prep_kernel(const float* __restrict__ x, const float* __restrict__ y) {
    int wid = threadIdx.x >> 5, l = threadIdx.x & 31;
    int rg = blockIdx.x * 8 + wid;
    bool isx = rg < NROWS;
    int row = isx ? rg : rg - NROWS;
    const float2* src = reinterpret_cast<const float2*>(isx ? x : y);

    float2 v = src[(size_t)row * 32 + l];
    __half h0 = __float2half_rn(v.x);
    __half h1 = __float2half_rn(v.y);
    __half l0 = __float2half_rn(v.x - __half2float(h0));
    __half l1 = __float2half_rn(v.y - __half2float(h1));
    uint32_t hi = pack_h2(h0, h1);
    uint32_t lo = pack_h2(l0, l1);

    int ks = l >> 3;               // k-chunk 0..3 (kk = 2*(l&7) within chunk)
    int khi = (l >> 2) & 1;        // kk >= 8 ?

    if (isx) {
        // A frag regs: j0=(r0,klow) j1=(r0+8,klow) j2=(r0,khigh) j3=(r0+8,khigh)
        int b = row >> 4, wr = row & 15;
        int lane_t = ((wr & 7) << 2) | (l & 3);
        int j = (khi << 1) | (wr >> 3);
        uint32_t* A32 = reinterpret_cast<uint32_t*>(g_Af);
        size_t base = (((((size_t)b * 4 + ks) * 2 + 0) * 32 + lane_t) * 4) + j;
        A32[base] = hi;
        A32[base + 128] = lo;      // part stride = 32 lanes * 4 u32
    } else {
        // B frag: thread T of frag nf holds b0=(kpair 2q @ n=nf*8+T/4), b1=(+8)
        // uint4 components: {nf_even.b0, nf_even.b1, nf_odd.b0, nf_odd.b1}
        int nb = row >> 5, nw = row & 31, nf = nw >> 3, pp = nf >> 1;
        int L = ((nw & 7) << 2) | (l & 3);
        int c = ((nf & 1) << 1) | khi;
        uint32_t* B32 = reinterpret_cast<uint32_t*>(g_Bf);
        size_t base = ((((((size_t)nb * 4 + ks) * 2 + 0) * 2 + pp) * 32 + L) * 4) + c;
        B32[base] = hi;
        B32[base + 256] = lo;      // part stride = 2 pp * 32 lanes * 4 u32
    }

    float s = v.x * v.x + v.y * v.y;
    #pragma unroll
    for (int o = 16; o; o >>= 1) s += __shfl_xor_sync(0xffffffffu, s, o);
    if (l == 0) (isx ? g_xn : g_yn)[row] = s;
}

// ============================================================================
// main: 128x128 tile per CTA, 8 warps (2x4), warp tile 64x32.
// Fragments loaded straight from GMEM (LDG.128, coalesced); no operand smem.
// ============================================================================
__global__ __launch_bounds__(256, 2)
void rbf_kernel(const float* __restrict__ sigma, float* __restrict__ out) {
    __shared__ float s_xn[TILE], s_yn[TILE];

    int tid = threadIdx.x;
    int tile_n = blockIdx.x, tile_m = blockIdx.y;

    if (tid < TILE)       s_xn[tid]        = g_xn[tile_m * TILE + tid];
    else                  s_yn[tid - TILE] = g_yn[tile_n * TILE + tid - TILE];
    __syncthreads();

    int w = tid >> 5, lane = tid & 31;
    int warp_m = w >> 2, warp_n = w & 3;
    int m_base = warp_m * 64, n_base = warp_n * 32;

    int bA0 = tile_m * 8 + warp_m * 4;     // block16 index for mf=0
    int nb  = tile_n * 4 + warp_n;         // nblock32 index

    float acc[4][4][4];
    #pragma unroll
    for (int mf = 0; mf < 4; ++mf)
        #pragma unroll
        for (int nf = 0; nf < 4; ++nf)
            #pragma unroll
            for (int r = 0; r < 4; ++r) acc[mf][nf][r] = 0.f;

    #pragma unroll 1
    for (int ks = 0; ks < 4; ++ks) {
        // A fragments: one LDG.128 per (mf, part)
        uint4 ah[4], al[4];
        #pragma unroll
        for (int mf = 0; mf < 4; ++mf) {
            size_t o = ((((size_t)(bA0 + mf) * 4 + ks) * 2) * 32) + lane;
            ah[mf] = g_Af[o];
            al[mf] = g_Af[o + 32];
        }
        // B fragments: 4 LDG.128 (part x nfpair)
        size_t ob = (((size_t)nb * 4 + ks) * 4) * 32 + lane;   // (nb*4+ks)*2*2*32
        uint4 bh0 = g_Bf[ob];
        uint4 bh1 = g_Bf[ob + 32];
        uint4 bl0 = g_Bf[ob + 64];
        uint4 bl1 = g_Bf[ob + 96];

        uint32_t bh[4][2] = {{bh0.x, bh0.y}, {bh0.z, bh0.w}, {bh1.x, bh1.y}, {bh1.z, bh1.w}};
        uint32_t bl[4][2] = {{bl0.x, bl0.y}, {bl0.z, bl0.w}, {bl1.x, bl1.y}, {bl1.z, bl1.w}};

        // three 16-MMA sweeps: hi*hi, hi*lo, lo*hi
        #pragma unroll
        for (int mf = 0; mf < 4; ++mf)
            #pragma unroll
            for (int nf = 0; nf < 4; ++nf)
                mma16816(acc[mf][nf], reinterpret_cast<const uint32_t*>(&ah[mf]), bh[nf]);
        #pragma unroll
        for (int mf = 0; mf < 4; ++mf)
            #pragma unroll
            for (int nf = 0; nf < 4; ++nf)
                mma16816(acc[mf][nf], reinterpret_cast<const uint32_t*>(&ah[mf]), bl[nf]);
        #pragma unroll
        for (int mf = 0; mf < 4; ++mf)
            #pragma unroll
            for (int nf = 0; nf < 4; ++nf)
                mma16816(acc[mf][nf], reinterpret_cast<const uint32_t*>(&al[mf]), bh[nf]);
    }

    // fused epilogue (R9): q = max(xn+yn-2c, 0); out = exp2(q * -0.5/ln2/sg^2)
    float sg = *sigma;
    float k2 = -0.7213475204444817f / (sg * sg);
    int r0 = lane >> 2;
    int c0 = (lane & 3) * 2;

    size_t out_row0 = (size_t)(tile_m * TILE + m_base + r0) * 8192u
                    + (size_t)(tile_n * TILE + n_base + c0);
    #pragma unroll
    for (int mf = 0; mf < 4; ++mf) {
        float xnA = s_xn[m_base + mf * 16 + r0];
        float xnB = s_xn[m_base + mf * 16 + r0 + 8];
        #pragma unroll
        for (int nf = 0; nf < 4; ++nf) {
            int col = n_base + nf * 8 + c0;
            float yn0 = s_yn[col], yn1 = s_yn[col + 1];
            float* d = acc[mf][nf];
            float q0 = fmaxf(fmaf(-2.f, d[0], xnA + yn0), 0.f);
            float q1 = fmaxf(fmaf(-2.f, d[1], xnA + yn1), 0.f);
            float q2 = fmaxf(fmaf(-2.f, d[2], xnB + yn0), 0.f);
            float q3 = fmaxf(fmaf(-2.f, d[3], xnB + yn1), 0.f);
            float2 o01, o23;
            o01.x = exp2f(q0 * k2); o01.y = exp2f(q1 * k2);
            o23.x = exp2f(q2 * k2); o23.y = exp2f(q3 * k2);
            size_t base = out_row0 + (size_t)(mf * 16) * 8192u + (size_t)(nf * 8);
            *reinterpret_cast<float2*>(out + base)               = o01;
            *reinterpret_cast<float2*>(out + base + 8u * 8192u)  = o23;
        }
    }
}

// ============================================================================
extern "C" void kernel_launch(void* const* d_in, const int* in_sizes, int n_in,
                              void* d_out, int out_size) {
    (void)in_sizes; (void)n_in; (void)out_size;
    const float* x     = (const float*)d_in[0];
    const float* y     = (const float*)d_in[1];
    const float* sigma = (const float*)d_in[2];
    float* out = (float*)d_out;

    prep_kernel<<<(2 * NROWS) / 8, 256>>>(x, y);
    rbf_kernel<<<dim3(NROWS / TILE, NROWS / TILE), 256>>>(sigma, out);
}